// round 13
// baseline (speedup 1.0000x reference)
#include <cuda_runtime.h>
#include <math_constants.h>

// Problem constants
#define B_    32
#define L_    1000
#define NCHAR 256
#define DM    512
#define NH    8
#define DH    64
#define XROWS (NCHAR + L_)   // 1256
#define XPAD  1280
#define NI    (NH * B_)      // 256 rows, i = s*8 + h (s = length-rank of b)
#define LN10000 9.210340371976184f
#define PE_K  (-LN10000 / (float)DM)

// Split-K factors (R6 values — proven best)
#define DSPLIT 4
#define YSPLIT 8
#define DCHUNK (DM / DSPLIT)      // 128
#define YCHUNK (XPAD / YSPLIT)    // 160

// Setup grid layout
#define EMB_BLKS 32
#define PE_BLKS  125
#define SETUP_BLKS (EMB_BLKS + PE_BLKS + 1 + NI)   // 414

// Scratch (device globals: no allocation allowed)
__device__ float g_X  [XPAD * DM];
__device__ float g_u  [NI * DM];
__device__ float g_dotp[DSPLIT][NI * XPAD];
__device__ float g_wr [NI * XPAD];           // pad tail stays 0 (zero-init BSS)
__device__ float g_yp [YSPLIT][NI * DM];
__device__ int   g_sb[B_];                   // g_sb[s] = batch with length-rank s
__device__ int   g_rank[B_];                 // g_rank[b] = rank of batch b
__device__ int   g_lensorted[B_];            // ascending clamped lengths

__device__ __forceinline__ int clamp_len(int l) {
    if (l < 1) l = 1;
    if (l > L_) l = L_;
    return l;
}

// ---------------------------------------------------------------------------
// Kernel 1 (merged setup): emb copy / pe rows / pad+sort-stats / fused q+u
// ---------------------------------------------------------------------------
__global__ void setup_kernel(const int* __restrict__ data,
                             const int* __restrict__ lengths,
                             const float* __restrict__ emb,
                             const float* __restrict__ Wq,
                             const float* __restrict__ bq,
                             const float* __restrict__ Wk) {
    int blk = blockIdx.x;
    int tid = threadIdx.x;           // 256
    __shared__ float xs[DM];
    __shared__ float qs[DH];
    __shared__ int   sl[B_];
    __shared__ int   ssel;

    if (blk < EMB_BLKS) {
        int r0 = blk * 8;
        #pragma unroll
        for (int rr = 0; rr < 8; rr++)
            ((float2*)g_X)[(size_t)(r0 + rr) * 256 + tid] =
                ((const float2*)emb)[(size_t)(r0 + rr) * 256 + tid];
        return;
    }
    if (blk < EMB_BLKS + PE_BLKS) {
        int t0 = (blk - EMB_BLKS) * 8;
        float div = expf((float)(2 * tid) * PE_K);
        float s, c, sd, cd;
        sincosf((float)t0 * div, &s, &c);
        sincosf(div, &sd, &cd);
        #pragma unroll
        for (int rr = 0; rr < 8; rr++) {
            ((float2*)g_X)[(size_t)(NCHAR + t0 + rr) * 256 + tid] = make_float2(s, c);
            float s2 = s * cd + c * sd;
            float c2 = c * cd - s * sd;
            s = s2; c = c2;
        }
        return;
    }
    if (blk == EMB_BLKS + PE_BLKS) {
        // zero pad rows of X + publish sort stats
        for (int r = XROWS; r < XPAD; r++)
            ((float2*)g_X)[(size_t)r * 256 + tid] = make_float2(0.f, 0.f);
        if (tid < B_) sl[tid] = clamp_len(lengths[tid]);
        __syncthreads();
        if (tid < B_) {
            int l = sl[tid];
            int r = 0;
            #pragma unroll
            for (int b2 = 0; b2 < B_; b2++) {
                int l2 = sl[b2];
                r += (l2 < l) || (l2 == l && b2 < tid);
            }
            g_rank[tid] = r;
            g_sb[r] = tid;
            g_lensorted[r] = l;
        }
        return;
    }

    // --- fused q+u for row i = s*8 + h ---
    int i = blk - (EMB_BLKS + PE_BLKS + 1);
    int s_ = i >> 3;                 // length rank
    int h  = i & 7;
    int w = tid >> 5, lane = tid & 31;

    if (tid < B_) sl[tid] = clamp_len(lengths[tid]);
    __syncthreads();
    if (tid < B_) {
        int l = sl[tid];
        int r = 0;
        #pragma unroll
        for (int b2 = 0; b2 < B_; b2++) {
            int l2 = sl[b2];
            r += (l2 < l) || (l2 == l && b2 < tid);
        }
        if (r == s_) ssel = tid;
    }
    __syncthreads();
    int b = ssel;

    int p = sl[b] - 1;
    int ch = data[(size_t)b * L_ + p] & (NCHAR - 1);

    {
        int e0 = 2 * tid;
        float div = expf((float)e0 * PE_K);
        float sn, cn;
        sincosf((float)p * div, &sn, &cn);
        float2 ev = *(const float2*)(emb + (size_t)ch * DM + e0);
        xs[e0]     = ev.x + sn;
        xs[e0 + 1] = ev.y + cn;
    }
    __syncthreads();

    for (int d = w * 8; d < w * 8 + 8; d++) {
        int j = h * DH + d;
        const float* wr = Wq + (size_t)j * DM;
        float sacc = 0.f;
        #pragma unroll
        for (int e0 = lane * 4; e0 < DM; e0 += 128) {
            float4 a = *(const float4*)(wr + e0);
            float4 x4 = *(const float4*)(xs + e0);
            sacc += a.x * x4.x + a.y * x4.y + a.z * x4.z + a.w * x4.w;
        }
        #pragma unroll
        for (int off = 16; off; off >>= 1) sacc += __shfl_xor_sync(0xffffffffu, sacc, off);
        if (lane == 0) qs[d] = sacc + bq[j];
    }
    __syncthreads();

    int e0 = tid * 2;
    float a0 = 0.f, a1 = 0.f;
    const float* Wbase = Wk + (size_t)(h * DH) * DM;
    #pragma unroll 8
    for (int d = 0; d < DH; d++) {
        float qd = qs[d];
        float2 wv = *(const float2*)(Wbase + (size_t)d * DM + e0);
        a0 += qd * wv.x;
        a1 += qd * wv.y;
    }
    *(float2*)(g_u + (size_t)i * DM + e0) = make_float2(a0, a1);
}

// ---------------------------------------------------------------------------
// Kernel 2: D partials = U @ X^T (NT), skip n-tiles beyond NCHAR+maxcnt.
// grid (XPAD/64, NI/64, DSPLIT), 256 threads, 4x4 tile, double-buffered.
// ---------------------------------------------------------------------------
#define BM 64
#define BN 64
#define BK 16
__global__ void d_gemm_kernel() {
    int m0 = blockIdx.y * BM;
    int n0 = blockIdx.x * BN;
    int kb = blockIdx.z * DCHUNK;

    int maxcnt = g_lensorted[(m0 >> 3) + 7];   // rows sorted ascending by length
    if (n0 >= NCHAR + maxcnt) return;          // D there is never read

    __shared__ float As[2][BK][BM + 4];
    __shared__ float Bs[2][BK][BN + 4];

    int tid  = threadIdx.x;
    int lrow = tid >> 2;
    int lcol = (tid & 3) * 4;
    int ty = tid >> 4;
    int tx = tid & 15;

    const float* Aptr = g_u + (size_t)(m0 + lrow) * DM + lcol;
    const float* Bptr = g_X + (size_t)(n0 + lrow) * DM + lcol;

    float4 a_n = *(const float4*)(Aptr + kb);
    float4 b_n = *(const float4*)(Bptr + kb);
    #pragma unroll
    for (int q = 0; q < 4; q++) {
        As[0][lcol + q][lrow] = ((const float*)&a_n)[q];
        Bs[0][lcol + q][lrow] = ((const float*)&b_n)[q];
    }
    __syncthreads();

    float acc[4][4] = {};
    const int NIT = DCHUNK / BK;     // 8

    for (int it = 0; it < NIT; it++) {
        int cur = it & 1, nxt = cur ^ 1;
        if (it + 1 < NIT) {
            a_n = *(const float4*)(Aptr + kb + (it + 1) * BK);
            b_n = *(const float4*)(Bptr + kb + (it + 1) * BK);
        }
        #pragma unroll
        for (int kk = 0; kk < BK; kk++) {
            float4 a4 = *(const float4*)&As[cur][kk][ty * 4];
            float4 b4 = *(const float4*)&Bs[cur][kk][tx * 4];
            float a[4] = {a4.x, a4.y, a4.z, a4.w};
            float b[4] = {b4.x, b4.y, b4.z, b4.w};
            #pragma unroll
            for (int ii = 0; ii < 4; ii++)
                #pragma unroll
                for (int jj = 0; jj < 4; jj++)
                    acc[ii][jj] += a[ii] * b[jj];
        }
        if (it + 1 < NIT) {
            #pragma unroll
            for (int q = 0; q < 4; q++) {
                As[nxt][lcol + q][lrow] = ((const float*)&a_n)[q];
                Bs[nxt][lcol + q][lrow] = ((const float*)&b_n)[q];
            }
            __syncthreads();
        }
    }

    float* outp = g_dotp[blockIdx.z];
    #pragma unroll
    for (int ii = 0; ii < 4; ii++) {
        int r = m0 + ty * 4 + ii;
        #pragma unroll
        for (int jj = 0; jj < 4; jj++)
            outp[(size_t)r * XPAD + n0 + tx * 4 + jj] = acc[ii][jj] * 0.125f;
    }
}

// ---------------------------------------------------------------------------
// Kernel 3: per row i = s*8+h softmax + char binning. 256 blocks.
// ---------------------------------------------------------------------------
__global__ void softmax_bin_kernel(const int* __restrict__ data,
                                   const int* __restrict__ lengths) {
    int i = blockIdx.x;          // row index
    int s_ = i >> 3;
    int b = g_sb[s_];
    __shared__ float s[L_];
    __shared__ float dch[NCHAR];
    __shared__ float bins[NCHAR];
    __shared__ float red[8];

    int tid = threadIdx.x;       // 256
    int count = clamp_len(lengths[b]);

    size_t base = (size_t)i * XPAD;

    {
        float v = 0.f;
        #pragma unroll
        for (int z = 0; z < DSPLIT; z++) v += g_dotp[z][base + tid];
        dch[tid] = v;
        bins[tid] = 0.f;
    }
    __syncthreads();

    float lm = -CUDART_INF_F;
    for (int t = tid; t < count; t += 256) {
        int c = data[(size_t)b * L_ + t] & (NCHAR - 1);
        float v = dch[c];
        #pragma unroll
        for (int z = 0; z < DSPLIT; z++) v += g_dotp[z][base + NCHAR + t];
        s[t] = v;
        lm = fmaxf(lm, v);
    }
    #pragma unroll
    for (int off = 16; off; off >>= 1) lm = fmaxf(lm, __shfl_xor_sync(0xffffffffu, lm, off));
    if ((tid & 31) == 0) red[tid >> 5] = lm;
    __syncthreads();
    float M = -CUDART_INF_F;
    #pragma unroll
    for (int k = 0; k < 8; k++) M = fmaxf(M, red[k]);
    __syncthreads();

    float ls = 0.f;
    for (int t = tid; t < count; t += 256) {
        float e = __expf(s[t] - M);
        s[t] = e;
        ls += e;
    }
    #pragma unroll
    for (int off = 16; off; off >>= 1) ls += __shfl_xor_sync(0xffffffffu, ls, off);
    if ((tid & 31) == 0) red[tid >> 5] = ls;
    __syncthreads();
    float S = 0.f;
    #pragma unroll
    for (int k = 0; k < 8; k++) S += red[k];
    float inv = 1.f / S;

    float* WR = g_wr + base;
    for (int t = tid; t < L_; t += 256) {
        float w = 0.f;
        if (t < count) {
            w = s[t] * inv;
            atomicAdd(&bins[data[(size_t)b * L_ + t] & (NCHAR - 1)], w);
        }
        WR[NCHAR + t] = w;
    }
    __syncthreads();
    WR[tid] = bins[tid];
    // WR[XROWS..XPAD) never written; stays 0 (matching zero X pad rows)
}

// ---------------------------------------------------------------------------
// Kernel 4: Y partials = WR @ X (NN), K truncated at NCHAR+maxcnt per m-tile.
// grid (DM/64, NI/64, YSPLIT), 256 threads, 4x4 tile, double-buffered.
// ---------------------------------------------------------------------------
__global__ void y_gemm_kernel() {
    int m0 = blockIdx.y * BM;
    int n0 = blockIdx.x * BN;
    int kb = blockIdx.z * YCHUNK;

    int maxk = NCHAR + g_lensorted[(m0 >> 3) + 7];   // exclusive useful-k bound
    int kend = kb + YCHUNK;
    {
        int kcap = ((maxk + BK - 1) / BK) * BK;       // round up to BK
        if (kcap < kend) kend = kcap;
    }
    int nit = (kend - kb) / BK;

    __shared__ float As[2][BK][BM + 4];
    __shared__ float Bs[2][BK][BN + 4];

    int tid  = threadIdx.x;
    int lrow = tid >> 2;
    int lcol = (tid & 3) * 4;
    int br = tid >> 4;
    int bc = (tid & 15) * 4;
    int ty = tid >> 4;
    int tx = tid & 15;

    float acc[4][4] = {};

    if (nit > 0) {
        const float* Aptr = g_wr + (size_t)(m0 + lrow) * XPAD + lcol;

        float4 a_n = *(const float4*)(Aptr + kb);
        float4 b_n = *(const float4*)(g_X + (size_t)(kb + br) * DM + n0 + bc);
        #pragma unroll
        for (int q = 0; q < 4; q++)
            As[0][lcol + q][lrow] = ((const float*)&a_n)[q];
        *(float4*)&Bs[0][br][bc] = b_n;
        __syncthreads();

        for (int it = 0; it < nit; it++) {
            int cur = it & 1, nxt = cur ^ 1;
            if (it + 1 < nit) {
                int k0 = kb + (it + 1) * BK;
                a_n = *(const float4*)(Aptr + k0);
                b_n = *(const float4*)(g_X + (size_t)(k0 + br) * DM + n0 + bc);
            }
            #pragma unroll
            for (int kk = 0; kk < BK; kk++) {
                float4 a4 = *(const float4*)&As[cur][kk][ty * 4];
                float4 b4 = *(const float4*)&Bs[cur][kk][tx * 4];
                float a[4] = {a4.x, a4.y, a4.z, a4.w};
                float b[4] = {b4.x, b4.y, b4.z, b4.w};
                #pragma unroll
                for (int ii = 0; ii < 4; ii++)
                    #pragma unroll
                    for (int jj = 0; jj < 4; jj++)
                        acc[ii][jj] += a[ii] * b[jj];
            }
            if (it + 1 < nit) {
                #pragma unroll
                for (int q = 0; q < 4; q++)
                    As[nxt][lcol + q][lrow] = ((const float*)&a_n)[q];
                *(float4*)&Bs[nxt][br][bc] = b_n;
                __syncthreads();
            }
        }
    }

    float* outp = g_yp[blockIdx.z];
    #pragma unroll
    for (int ii = 0; ii < 4; ii++) {
        int r = m0 + ty * 4 + ii;
        #pragma unroll
        for (int jj = 0; jj < 4; jj++)
            outp[(size_t)r * DM + n0 + tx * 4 + jj] = acc[ii][jj];
    }
}

// ---------------------------------------------------------------------------
// Kernel 5 (fused): sum Y partials; ctx = Wv_h @ y + bv; MLP head.
// One block per batch, 256 threads (8 warps). Warp w == head w.
// ---------------------------------------------------------------------------
__global__ void ctx_mlp_kernel(const float* __restrict__ Wv,
                               const float* __restrict__ bv,
                               const float* __restrict__ W1,
                               const float* __restrict__ b1,
                               const float* __restrict__ W2,
                               const float* __restrict__ b2,
                               float* __restrict__ out) {
    int b = blockIdx.x;
    int s_ = g_rank[b];
    __shared__ float ys[NH][DM];
    __shared__ float cs[DM];
    __shared__ float hs[DM];
    __shared__ float o8[8];
    int tid = threadIdx.x;
    int w = tid >> 5, lane = tid & 31;

    for (int i4 = tid; i4 < NH * DM / 4; i4 += 256) {
        int h = i4 >> 7;
        int e4 = i4 & 127;
        int row = s_ * NH + h;
        float4 v = make_float4(0.f, 0.f, 0.f, 0.f);
        size_t off4 = ((size_t)row * DM) / 4 + e4;
        #pragma unroll
        for (int z = 0; z < YSPLIT; z++) {
            float4 p = ((const float4*)g_yp[z])[off4];
            v.x += p.x; v.y += p.y; v.z += p.z; v.w += p.w;
        }
        ((float4*)ys[h])[e4] = v;
    }
    __syncthreads();

    const float* yv = ys[w];
    for (int jj = 0; jj < DH; jj += 2) {
        int j0 = w * DH + jj;
        const float* w0 = Wv + (size_t)j0 * DM;
        const float* w1 = w0 + DM;
        float s0 = 0.f, s1 = 0.f;
        #pragma unroll
        for (int e0 = lane * 4; e0 < DM; e0 += 128) {
            float4 y4 = *(const float4*)(yv + e0);
            float4 a0 = *(const float4*)(w0 + e0);
            float4 a1 = *(const float4*)(w1 + e0);
            s0 += a0.x * y4.x + a0.y * y4.y + a0.z * y4.z + a0.w * y4.w;
            s1 += a1.x * y4.x + a1.y * y4.y + a1.z * y4.z + a1.w * y4.w;
        }
        #pragma unroll
        for (int off = 16; off; off >>= 1) {
            s0 += __shfl_xor_sync(0xffffffffu, s0, off);
            s1 += __shfl_xor_sync(0xffffffffu, s1, off);
        }
        if (lane == 0) {
            cs[j0]     = s0 + bv[j0];
            cs[j0 + 1] = s1 + bv[j0 + 1];
        }
    }
    __syncthreads();

    for (int jj = 0; jj < DH; jj += 2) {
        int j0 = w * DH + jj;
        const float* w0 = W1 + (size_t)j0 * DM;
        const float* w1 = w0 + DM;
        float s0 = 0.f, s1 = 0.f;
        #pragma unroll
        for (int e0 = lane * 4; e0 < DM; e0 += 128) {
            float4 c4 = *(const float4*)(cs + e0);
            float4 a0 = *(const float4*)(w0 + e0);
            float4 a1 = *(const float4*)(w1 + e0);
            s0 += a0.x * c4.x + a0.y * c4.y + a0.z * c4.z + a0.w * c4.w;
            s1 += a1.x * c4.x + a1.y * c4.y + a1.z * c4.z + a1.w * c4.w;
        }
        #pragma unroll
        for (int off = 16; off; off >>= 1) {
            s0 += __shfl_xor_sync(0xffffffffu, s0, off);
            s1 += __shfl_xor_sync(0xffffffffu, s1, off);
        }
        if (lane == 0) {
            float v0 = s0 + b1[j0];
            float v1 = s1 + b1[j0 + 1];
            hs[j0]     = (v0 > 0.f) ? v0 : 0.01f * v0;
            hs[j0 + 1] = (v1 > 0.f) ? v1 : 0.01f * v1;
        }
    }
    __syncthreads();

    {
        const float* wr = W2 + (size_t)w * DM;
        float s = 0.f;
        #pragma unroll
        for (int e0 = lane * 4; e0 < DM; e0 += 128) {
            float4 a = *(const float4*)(wr + e0);
            float4 h4 = *(const float4*)(hs + e0);
            s += a.x * h4.x + a.y * h4.y + a.z * h4.z + a.w * h4.w;
        }
        #pragma unroll
        for (int off = 16; off; off >>= 1) s += __shfl_xor_sync(0xffffffffu, s, off);
        if (lane == 0) {
            float v = s + b2[w];
            o8[w] = (v > 0.f) ? v : 0.f;
        }
    }
    __syncthreads();
    if (tid == 0) {
        float mv = 0.f;
        #pragma unroll
        for (int k = 0; k < 8; k++) mv += o8[k];
        mv *= 0.125f;
        out[b] = (mv > 0.f) ? mv : 0.01f * mv;
    }
}

// ---------------------------------------------------------------------------
extern "C" void kernel_launch(void* const* d_in, const int* in_sizes, int n_in,
                              void* d_out, int out_size) {
    const int* data    = (const int*)d_in[0];    // int32 (JAX x64 disabled)
    const int* lengths = (const int*)d_in[1];
    const float* emb = (const float*)d_in[2];
    const float* Wq  = (const float*)d_in[3];
    const float* bq  = (const float*)d_in[4];
    const float* Wk  = (const float*)d_in[5];
    // d_in[6] = bk: drops out of softmax (constant shift per row)
    const float* Wv  = (const float*)d_in[7];
    const float* bv  = (const float*)d_in[8];
    const float* W1  = (const float*)d_in[9];
    const float* b1  = (const float*)d_in[10];
    const float* W2  = (const float*)d_in[11];
    const float* b2  = (const float*)d_in[12];
    float* out = (float*)d_out;

    setup_kernel<<<SETUP_BLKS, 256>>>(data, lengths, emb, Wq, bq, Wk);
    d_gemm_kernel<<<dim3(XPAD / BN, NI / BM, DSPLIT), 256>>>();
    softmax_bin_kernel<<<NI, 256>>>(data, lengths);
    y_gemm_kernel<<<dim3(DM / BN, NI / BM, YSPLIT), 256>>>();
    ctx_mlp_kernel<<<B_, 256>>>(Wv, bv, W1, b1, W2, b2, out);
}

// round 15
// speedup vs baseline: 1.0243x; 1.0243x over previous
#include <cuda_runtime.h>
#include <math_constants.h>

// Problem constants
#define B_    32
#define L_    1000
#define NCHAR 256
#define DM    512
#define NH    8
#define DH    64
#define XROWS (NCHAR + L_)   // 1256
#define XPAD  1280           // padded row count (multiple of 64), pad rows zero
#define NI    (NH * B_)      // 256 (h,b) pairs
#define LN10000 9.210340371976184f
#define PE_K  (-LN10000 / (float)DM)

// Split-K factors (R6 values — proven best)
#define DSPLIT 4
#define YSPLIT 8
#define DCHUNK (DM / DSPLIT)      // 128
#define YCHUNK (XPAD / YSPLIT)    // 160

// Setup grid layout
#define EMB_BLKS 32               // 8 emb rows each
#define PE_BLKS  125              // 8 pe rows each
#define SETUP_BLKS (EMB_BLKS + PE_BLKS + 1 + NI)   // 414

// Scratch (device globals: no allocation allowed)
__device__ float g_X  [XPAD * DM];           // [emb(256) ; pe(1000) ; zeros(24)]
__device__ float g_u  [NI * DM];             // U[i=h*32+b][e] = q[b,h] @ Wk_head
__device__ float g_dotp[DSPLIT][NI * XPAD];  // K-split partials of D = U @ X^T * scale
__device__ float g_wr [NI * XPAD];           // WR[i][r] softmax weight rows (pad stays 0)
__device__ float g_yp [YSPLIT][NI * DM];     // K-split partials of Y = WR @ X

// ---------------------------------------------------------------------------
// Kernel 1 (merged setup): emb copy / pe rows (rotation recurrence) / pad /
// fused q+u per (h,b).
// ---------------------------------------------------------------------------
__global__ void setup_kernel(const int* __restrict__ data,
                             const int* __restrict__ lengths,
                             const float* __restrict__ emb,
                             const float* __restrict__ Wq,
                             const float* __restrict__ bq,
                             const float* __restrict__ Wk) {
    int blk = blockIdx.x;
    int tid = threadIdx.x;           // 256

    if (blk < EMB_BLKS) {
        int r0 = blk * 8;
        #pragma unroll
        for (int rr = 0; rr < 8; rr++)
            ((float2*)g_X)[(size_t)(r0 + rr) * 256 + tid] =
                ((const float2*)emb)[(size_t)(r0 + rr) * 256 + tid];
        return;
    }
    if (blk < EMB_BLKS + PE_BLKS) {
        // 8 pe rows via rotation recurrence; thread owns pair tid
        int t0 = (blk - EMB_BLKS) * 8;
        float div = expf((float)(2 * tid) * PE_K);
        float s, c, sd, cd;
        sincosf((float)t0 * div, &s, &c);
        sincosf(div, &sd, &cd);
        #pragma unroll
        for (int rr = 0; rr < 8; rr++) {
            ((float2*)g_X)[(size_t)(NCHAR + t0 + rr) * 256 + tid] = make_float2(s, c);
            float s2 = s * cd + c * sd;
            float c2 = c * cd - s * sd;
            s = s2; c = c2;
        }
        return;
    }
    if (blk == EMB_BLKS + PE_BLKS) {
        for (int r = XROWS; r < XPAD; r++)
            ((float2*)g_X)[(size_t)r * 256 + tid] = make_float2(0.f, 0.f);
        return;
    }

    // --- fused q+u for i = blk - (EMB_BLKS+PE_BLKS+1) ---
    int i = blk - (EMB_BLKS + PE_BLKS + 1);
    int h = i >> 5;                  // i = h*32 + b
    int b = i & 31;
    __shared__ float xs[DM];
    __shared__ float qs[DH];
    int w = tid >> 5, lane = tid & 31;

    int p = lengths[b] - 1;
    if (p < 0) p = 0;
    if (p >= L_) p = L_ - 1;
    int ch = data[(size_t)b * L_ + p] & (NCHAR - 1);

    {
        int e0 = 2 * tid;
        float div = expf((float)e0 * PE_K);
        float s, c;
        sincosf((float)p * div, &s, &c);
        float2 ev = *(const float2*)(emb + (size_t)ch * DM + e0);
        xs[e0]     = ev.x + s;
        xs[e0 + 1] = ev.y + c;
    }
    __syncthreads();

    // qh rows: warp w handles d = w*8 .. w*8+7
    for (int d = w * 8; d < w * 8 + 8; d++) {
        int j = h * DH + d;
        const float* wr = Wq + (size_t)j * DM;
        float s = 0.f;
        #pragma unroll
        for (int e0 = lane * 4; e0 < DM; e0 += 128) {
            float4 a = *(const float4*)(wr + e0);
            float4 x4 = *(const float4*)(xs + e0);
            s += a.x * x4.x + a.y * x4.y + a.z * x4.z + a.w * x4.w;
        }
        #pragma unroll
        for (int off = 16; off; off >>= 1) s += __shfl_xor_sync(0xffffffffu, s, off);
        if (lane == 0) qs[d] = s + bq[j];
    }
    __syncthreads();

    // U row: thread owns 2 consecutive e
    int e0 = tid * 2;
    float a0 = 0.f, a1 = 0.f;
    const float* Wbase = Wk + (size_t)(h * DH) * DM;
    #pragma unroll 8
    for (int d = 0; d < DH; d++) {
        float qd = qs[d];
        float2 wv = *(const float2*)(Wbase + (size_t)d * DM + e0);
        a0 += qd * wv.x;
        a1 += qd * wv.y;
    }
    *(float2*)(g_u + (size_t)i * DM + e0) = make_float2(a0, a1);
}

// ---------------------------------------------------------------------------
// Kernel 2: D partials = U @ X^T (NT GEMM, scaled), K split by DSPLIT.
// Double-buffered. grid (XPAD/64, NI/64, DSPLIT), 256 threads, 4x4 tile.
// ---------------------------------------------------------------------------
#define BM 64
#define BN 64
#define BK 16
__global__ void d_gemm_kernel() {
    int m0 = blockIdx.y * BM;
    int n0 = blockIdx.x * BN;
    int kb = blockIdx.z * DCHUNK;

    __shared__ float As[2][BK][BM + 4];
    __shared__ float Bs[2][BK][BN + 4];

    int tid  = threadIdx.x;          // 256
    int lrow = tid >> 2;             // 0..63
    int lcol = (tid & 3) * 4;        // 0,4,8,12
    int ty = tid >> 4;               // 0..15
    int tx = tid & 15;               // 0..15

    const float* Aptr = g_u + (size_t)(m0 + lrow) * DM + lcol;
    const float* Bptr = g_X + (size_t)(n0 + lrow) * DM + lcol;

    float4 a_n = *(const float4*)(Aptr + kb);
    float4 b_n = *(const float4*)(Bptr + kb);
    #pragma unroll
    for (int q = 0; q < 4; q++) {
        As[0][lcol + q][lrow] = ((const float*)&a_n)[q];
        Bs[0][lcol + q][lrow] = ((const float*)&b_n)[q];
    }
    __syncthreads();

    float acc[4][4] = {};
    const int NIT = DCHUNK / BK;     // 8

    for (int it = 0; it < NIT; it++) {
        int cur = it & 1, nxt = cur ^ 1;
        if (it + 1 < NIT) {
            a_n = *(const float4*)(Aptr + kb + (it + 1) * BK);
            b_n = *(const float4*)(Bptr + kb + (it + 1) * BK);
        }
        #pragma unroll
        for (int kk = 0; kk < BK; kk++) {
            float4 a4 = *(const float4*)&As[cur][kk][ty * 4];
            float4 b4 = *(const float4*)&Bs[cur][kk][tx * 4];
            float a[4] = {a4.x, a4.y, a4.z, a4.w};
            float b[4] = {b4.x, b4.y, b4.z, b4.w};
            #pragma unroll
            for (int i = 0; i < 4; i++)
                #pragma unroll
                for (int j = 0; j < 4; j++)
                    acc[i][j] += a[i] * b[j];
        }
        if (it + 1 < NIT) {
            #pragma unroll
            for (int q = 0; q < 4; q++) {
                As[nxt][lcol + q][lrow] = ((const float*)&a_n)[q];
                Bs[nxt][lcol + q][lrow] = ((const float*)&b_n)[q];
            }
            __syncthreads();
        }
    }

    float* outp = g_dotp[blockIdx.z];
    #pragma unroll
    for (int i = 0; i < 4; i++) {
        int r = m0 + ty * 4 + i;
        float4 v = make_float4(acc[i][0] * 0.125f, acc[i][1] * 0.125f,
                               acc[i][2] * 0.125f, acc[i][3] * 0.125f);
        *(float4*)(outp + (size_t)r * XPAD + n0 + tx * 4) = v;
    }
}

// ---------------------------------------------------------------------------
// Kernel 3: per (h,b) softmax over valid positions + char binning.
// ---------------------------------------------------------------------------
__global__ void softmax_bin_kernel(const int* __restrict__ data,
                                   const int* __restrict__ lengths) {
    int h = blockIdx.x;
    int b = blockIdx.y;
    int i = h * B_ + b;
    __shared__ float s[L_];
    __shared__ float dch[NCHAR];
    __shared__ float bins[NCHAR];
    __shared__ float red[8];

    int tid = threadIdx.x;       // 256
    int count = lengths[b];
    if (count < 1) count = 1;
    if (count > L_) count = L_;

    size_t base = (size_t)i * XPAD;

    {
        float v = 0.f;
        #pragma unroll
        for (int z = 0; z < DSPLIT; z++) v += g_dotp[z][base + tid];
        dch[tid] = v;
        bins[tid] = 0.f;
    }
    __syncthreads();

    float lm = -CUDART_INF_F;
    for (int t = tid; t < count; t += 256) {
        int c = data[(size_t)b * L_ + t] & (NCHAR - 1);
        float v = dch[c];
        #pragma unroll
        for (int z = 0; z < DSPLIT; z++) v += g_dotp[z][base + NCHAR + t];
        s[t] = v;
        lm = fmaxf(lm, v);
    }
    #pragma unroll
    for (int off = 16; off; off >>= 1) lm = fmaxf(lm, __shfl_xor_sync(0xffffffffu, lm, off));
    if ((tid & 31) == 0) red[tid >> 5] = lm;
    __syncthreads();
    float M = -CUDART_INF_F;
    #pragma unroll
    for (int k = 0; k < 8; k++) M = fmaxf(M, red[k]);
    __syncthreads();

    float ls = 0.f;
    for (int t = tid; t < count; t += 256) {
        float e = __expf(s[t] - M);
        s[t] = e;
        ls += e;
    }
    #pragma unroll
    for (int off = 16; off; off >>= 1) ls += __shfl_xor_sync(0xffffffffu, ls, off);
    if ((tid & 31) == 0) red[tid >> 5] = ls;
    __syncthreads();
    float S = 0.f;
    #pragma unroll
    for (int k = 0; k < 8; k++) S += red[k];
    float inv = 1.f / S;

    float* WR = g_wr + base;
    for (int t = tid; t < L_; t += 256) {
        float w = 0.f;
        if (t < count) {
            w = s[t] * inv;
            atomicAdd(&bins[data[(size_t)b * L_ + t] & (NCHAR - 1)], w);
        }
        WR[NCHAR + t] = w;
    }
    __syncthreads();
    WR[tid] = bins[tid];
    // pad rows of g_X are zero, so WR[XROWS..XPAD) never contributes (stays 0)
}

// ---------------------------------------------------------------------------
// Kernel 4: Y partials = WR @ X (NN GEMM), K split by YSPLIT. Double-buffered.
// grid (DM/64, NI/64, YSPLIT), 256 threads, 4x4 tile.
// ---------------------------------------------------------------------------
__global__ void y_gemm_kernel() {
    int m0 = blockIdx.y * BM;
    int n0 = blockIdx.x * BN;
    int kb = blockIdx.z * YCHUNK;

    __shared__ float As[2][BK][BM + 4];
    __shared__ float Bs[2][BK][BN + 4];

    int tid  = threadIdx.x;          // 256
    int lrow = tid >> 2;             // 0..63
    int lcol = (tid & 3) * 4;        // 0,4,8,12
    int br = tid >> 4;               // 0..15 (B tile row)
    int bc = (tid & 15) * 4;         // 0..60 (B tile col)
    int ty = tid >> 4;
    int tx = tid & 15;

    const float* Aptr = g_wr + (size_t)(m0 + lrow) * XPAD + lcol;

    float4 a_n = *(const float4*)(Aptr + kb);
    float4 b_n = *(const float4*)(g_X + (size_t)(kb + br) * DM + n0 + bc);
    #pragma unroll
    for (int q = 0; q < 4; q++)
        As[0][lcol + q][lrow] = ((const float*)&a_n)[q];
    *(float4*)&Bs[0][br][bc] = b_n;
    __syncthreads();

    float acc[4][4] = {};
    const int NIT = YCHUNK / BK;     // 10

    for (int it = 0; it < NIT; it++) {
        int cur = it & 1, nxt = cur ^ 1;
        if (it + 1 < NIT) {
            int k0 = kb + (it + 1) * BK;
            a_n = *(const float4*)(Aptr + k0);
            b_n = *(const float4*)(g_X + (size_t)(k0 + br) * DM + n0 + bc);
        }
        #pragma unroll
        for (int kk = 0; kk < BK; kk++) {
            float4 a4 = *(const float4*)&As[cur][kk][ty * 4];
            float4 b4 = *(const float4*)&Bs[cur][kk][tx * 4];
            float a[4] = {a4.x, a4.y, a4.z, a4.w};
            float b[4] = {b4.x, b4.y, b4.z, b4.w};
            #pragma unroll
            for (int ii = 0; ii < 4; ii++)
                #pragma unroll
                for (int jj = 0; jj < 4; jj++)
                    acc[ii][jj] += a[ii] * b[jj];
        }
        if (it + 1 < NIT) {
            #pragma unroll
            for (int q = 0; q < 4; q++)
                As[nxt][lcol + q][lrow] = ((const float*)&a_n)[q];
            *(float4*)&Bs[nxt][br][bc] = b_n;
            __syncthreads();
        }
    }

    float* outp = g_yp[blockIdx.z];
    #pragma unroll
    for (int ii = 0; ii < 4; ii++) {
        int r = m0 + ty * 4 + ii;
        *(float4*)(outp + (size_t)r * DM + n0 + tx * 4) =
            make_float4(acc[ii][0], acc[ii][1], acc[ii][2], acc[ii][3]);
    }
}

// ---------------------------------------------------------------------------
// Kernel 5 (fused): sum Y partials; ctx = per-head Wv_h @ y + bv; MLP head.
// One block per batch, 256 threads (8 warps). Warp w == head w.
// ---------------------------------------------------------------------------
__global__ void ctx_mlp_kernel(const float* __restrict__ Wv,
                               const float* __restrict__ bv,
                               const float* __restrict__ W1,
                               const float* __restrict__ b1,
                               const float* __restrict__ W2,
                               const float* __restrict__ b2,
                               float* __restrict__ out) {
    int b = blockIdx.x;
    __shared__ float ys[NH][DM];     // 16 KB
    __shared__ float cs[DM];
    __shared__ float hs[DM];
    __shared__ float o8[8];
    int tid = threadIdx.x;           // 256
    int w = tid >> 5, lane = tid & 31;

    // stage y for all 8 heads (sum YSPLIT partials), float4 granularity
    for (int i4 = tid; i4 < NH * DM / 4; i4 += 256) {
        int h = i4 >> 7;             // 128 float4 per head
        int e4 = i4 & 127;
        float4 v = make_float4(0.f, 0.f, 0.f, 0.f);
        size_t off4 = ((size_t)(h * B_ + b) * DM) / 4 + e4;
        #pragma unroll
        for (int z = 0; z < YSPLIT; z++) {
            float4 p = ((const float4*)g_yp[z])[off4];
            v.x += p.x; v.y += p.y; v.z += p.z; v.w += p.w;
        }
        ((float4*)ys[h])[e4] = v;
    }
    __syncthreads();

    // ctx rows: warp w handles head w (rows w*64 .. w*64+63), dual-row
    const float* yv = ys[w];
    for (int jj = 0; jj < DH; jj += 2) {
        int j0 = w * DH + jj;
        const float* w0 = Wv + (size_t)j0 * DM;
        const float* w1 = w0 + DM;
        float s0 = 0.f, s1 = 0.f;
        #pragma unroll
        for (int e0 = lane * 4; e0 < DM; e0 += 128) {
            float4 y4 = *(const float4*)(yv + e0);
            float4 a0 = *(const float4*)(w0 + e0);
            float4 a1 = *(const float4*)(w1 + e0);
            s0 += a0.x * y4.x + a0.y * y4.y + a0.z * y4.z + a0.w * y4.w;
            s1 += a1.x * y4.x + a1.y * y4.y + a1.z * y4.z + a1.w * y4.w;
        }
        #pragma unroll
        for (int off = 16; off; off >>= 1) {
            s0 += __shfl_xor_sync(0xffffffffu, s0, off);
            s1 += __shfl_xor_sync(0xffffffffu, s1, off);
        }
        if (lane == 0) {
            cs[j0]     = s0 + bv[j0];
            cs[j0 + 1] = s1 + bv[j0 + 1];
        }
    }
    __syncthreads();

    // layer 1: hs = lrelu(W1 @ cs + b1), dual-row
    for (int jj = 0; jj < DH; jj += 2) {
        int j0 = w * DH + jj;
        const float* w0 = W1 + (size_t)j0 * DM;
        const float* w1 = w0 + DM;
        float s0 = 0.f, s1 = 0.f;
        #pragma unroll
        for (int e0 = lane * 4; e0 < DM; e0 += 128) {
            float4 c4 = *(const float4*)(cs + e0);
            float4 a0 = *(const float4*)(w0 + e0);
            float4 a1 = *(const float4*)(w1 + e0);
            s0 += a0.x * c4.x + a0.y * c4.y + a0.z * c4.z + a0.w * c4.w;
            s1 += a1.x * c4.x + a1.y * c4.y + a1.z * c4.z + a1.w * c4.w;
        }
        #pragma unroll
        for (int off = 16; off; off >>= 1) {
            s0 += __shfl_xor_sync(0xffffffffu, s0, off);
            s1 += __shfl_xor_sync(0xffffffffu, s1, off);
        }
        if (lane == 0) {
            float v0 = s0 + b1[j0];
            float v1 = s1 + b1[j0 + 1];
            hs[j0]     = (v0 > 0.f) ? v0 : 0.01f * v0;
            hs[j0 + 1] = (v1 > 0.f) ? v1 : 0.01f * v1;
        }
    }
    __syncthreads();

    // layer 2: warp w -> output row w
    {
        const float* wr = W2 + (size_t)w * DM;
        float s = 0.f;
        #pragma unroll
        for (int e0 = lane * 4; e0 < DM; e0 += 128) {
            float4 a = *(const float4*)(wr + e0);
            float4 h4 = *(const float4*)(hs + e0);
            s += a.x * h4.x + a.y * h4.y + a.z * h4.z + a.w * h4.w;
        }
        #pragma unroll
        for (int off = 16; off; off >>= 1) s += __shfl_xor_sync(0xffffffffu, s, off);
        if (lane == 0) {
            float v = s + b2[w];
            o8[w] = (v > 0.f) ? v : 0.f;
        }
    }
    __syncthreads();
    if (tid == 0) {
        float mv = 0.f;
        #pragma unroll
        for (int k = 0; k < 8; k++) mv += o8[k];
        mv *= 0.125f;
        out[b] = (mv > 0.f) ? mv : 0.01f * mv;
    }
}

// ---------------------------------------------------------------------------
extern "C" void kernel_launch(void* const* d_in, const int* in_sizes, int n_in,
                              void* d_out, int out_size) {
    const int* data    = (const int*)d_in[0];    // int32 (JAX x64 disabled)
    const int* lengths = (const int*)d_in[1];
    const float* emb = (const float*)d_in[2];
    const float* Wq  = (const float*)d_in[3];
    const float* bq  = (const float*)d_in[4];
    const float* Wk  = (const float*)d_in[5];
    // d_in[6] = bk: drops out of softmax (constant shift per row)
    const float* Wv  = (const float*)d_in[7];
    const float* bv  = (const float*)d_in[8];
    const float* W1  = (const float*)d_in[9];
    const float* b1  = (const float*)d_in[10];
    const float* W2  = (const float*)d_in[11];
    const float* b2  = (const float*)d_in[12];
    float* out = (float*)d_out;

    setup_kernel<<<SETUP_BLKS, 256>>>(data, lengths, emb, Wq, bq, Wk);
    d_gemm_kernel<<<dim3(XPAD / BN, NI / BM, DSPLIT), 256>>>();
    softmax_bin_kernel<<<dim3(NH, B_), 256>>>(data, lengths);
    y_gemm_kernel<<<dim3(DM / BN, NI / BM, YSPLIT), 256>>>();
    ctx_mlp_kernel<<<B_, 256>>>(Wv, bv, W1, b1, W2, b2, out);
}

// round 17
// speedup vs baseline: 1.0360x; 1.0115x over previous
#include <cuda_runtime.h>
#include <math_constants.h>

// Problem constants
#define B_    32
#define L_    1000
#define NCHAR 256
#define DM    512
#define NH    8
#define DH    64
#define XROWS (NCHAR + L_)   // 1256
#define XPAD  1280           // padded row count (multiple of 64), pad rows zero
#define NI    (NH * B_)      // 256 (h,b) pairs
#define LN10000 9.210340371976184f
#define PE_K  (-LN10000 / (float)DM)

// Split-K factors (proven best)
#define DSPLIT 4
#define YSPLIT 8
#define DCHUNK (DM / DSPLIT)      // 128
#define YCHUNK (XPAD / YSPLIT)    // 160

// Setup grid layout
#define EMB_BLKS 32               // 8 emb rows each
#define PE_BLKS  125              // 8 pe rows each
#define SETUP_BLKS (EMB_BLKS + PE_BLKS + 1 + NI)   // 414

// Scratch (device globals: no allocation allowed)
__device__ float g_X  [XPAD * DM];           // [emb(256) ; pe(1000) ; zeros(24)]
__device__ float g_u  [NI * DM];             // U[i=h*32+b][e] = q[b,h] @ Wk_head
__device__ float g_dotp[DSPLIT][NI * XPAD];  // K-split partials of D = U @ X^T * scale
__device__ float g_wr [NI * XPAD];           // WR[i][r] softmax weight rows (pad stays 0)
__device__ float g_yp [YSPLIT][NI * DM];     // K-split partials of Y = WR @ X

// ---------------------------------------------------------------------------
// Kernel 1 (merged setup): emb copy / pe rows (rotation recurrence) / pad /
// fused q+u per (h,b).
// ---------------------------------------------------------------------------
__global__ void setup_kernel(const int* __restrict__ data,
                             const int* __restrict__ lengths,
                             const float* __restrict__ emb,
                             const float* __restrict__ Wq,
                             const float* __restrict__ bq,
                             const float* __restrict__ Wk) {
    int blk = blockIdx.x;
    int tid = threadIdx.x;           // 256

    if (blk < EMB_BLKS) {
        int r0 = blk * 8;
        #pragma unroll
        for (int rr = 0; rr < 8; rr++)
            ((float2*)g_X)[(size_t)(r0 + rr) * 256 + tid] =
                ((const float2*)emb)[(size_t)(r0 + rr) * 256 + tid];
        return;
    }
    if (blk < EMB_BLKS + PE_BLKS) {
        // 8 pe rows via rotation recurrence; thread owns pair tid
        int t0 = (blk - EMB_BLKS) * 8;
        float div = expf((float)(2 * tid) * PE_K);
        float s, c, sd, cd;
        sincosf((float)t0 * div, &s, &c);
        sincosf(div, &sd, &cd);
        #pragma unroll
        for (int rr = 0; rr < 8; rr++) {
            ((float2*)g_X)[(size_t)(NCHAR + t0 + rr) * 256 + tid] = make_float2(s, c);
            float s2 = s * cd + c * sd;
            float c2 = c * cd - s * sd;
            s = s2; c = c2;
        }
        return;
    }
    if (blk == EMB_BLKS + PE_BLKS) {
        for (int r = XROWS; r < XPAD; r++)
            ((float2*)g_X)[(size_t)r * 256 + tid] = make_float2(0.f, 0.f);
        return;
    }

    // --- fused q+u for i = blk - (EMB_BLKS+PE_BLKS+1) ---
    int i = blk - (EMB_BLKS + PE_BLKS + 1);
    int h = i >> 5;                  // i = h*32 + b
    int b = i & 31;
    __shared__ float xs[DM];
    __shared__ float qs[DH];
    int w = tid >> 5, lane = tid & 31;

    int p = lengths[b] - 1;
    if (p < 0) p = 0;
    if (p >= L_) p = L_ - 1;
    int ch = data[(size_t)b * L_ + p] & (NCHAR - 1);

    {
        int e0 = 2 * tid;
        float div = expf((float)e0 * PE_K);
        float s, c;
        sincosf((float)p * div, &s, &c);
        float2 ev = *(const float2*)(emb + (size_t)ch * DM + e0);
        xs[e0]     = ev.x + s;
        xs[e0 + 1] = ev.y + c;
    }
    __syncthreads();

    // qh rows: warp w handles d = w*8 .. w*8+7
    for (int d = w * 8; d < w * 8 + 8; d++) {
        int j = h * DH + d;
        const float* wr = Wq + (size_t)j * DM;
        float s = 0.f;
        #pragma unroll
        for (int e0 = lane * 4; e0 < DM; e0 += 128) {
            float4 a = *(const float4*)(wr + e0);
            float4 x4 = *(const float4*)(xs + e0);
            s += a.x * x4.x + a.y * x4.y + a.z * x4.z + a.w * x4.w;
        }
        #pragma unroll
        for (int off = 16; off; off >>= 1) s += __shfl_xor_sync(0xffffffffu, s, off);
        if (lane == 0) qs[d] = s + bq[j];
    }
    __syncthreads();

    // U row: thread owns 2 consecutive e
    int e0 = tid * 2;
    float a0 = 0.f, a1 = 0.f;
    const float* Wbase = Wk + (size_t)(h * DH) * DM;
    #pragma unroll 8
    for (int d = 0; d < DH; d++) {
        float qd = qs[d];
        float2 wv = *(const float2*)(Wbase + (size_t)d * DM + e0);
        a0 += qd * wv.x;
        a1 += qd * wv.y;
    }
    *(float2*)(g_u + (size_t)i * DM + e0) = make_float2(a0, a1);
}

// ---------------------------------------------------------------------------
// Kernel 2: D partials = U @ X^T (NT GEMM, scaled), K split by DSPLIT.
// Double-buffered. grid (XPAD/64, NI/64, DSPLIT), 256 threads, 4x4 tile.
// ---------------------------------------------------------------------------
#define BM 64
#define BN 64
#define BK 16
__global__ void d_gemm_kernel() {
    int m0 = blockIdx.y * BM;
    int n0 = blockIdx.x * BN;
    int kb = blockIdx.z * DCHUNK;

    __shared__ float As[2][BK][BM + 4];
    __shared__ float Bs[2][BK][BN + 4];

    int tid  = threadIdx.x;          // 256
    int lrow = tid >> 2;             // 0..63
    int lcol = (tid & 3) * 4;        // 0,4,8,12
    int ty = tid >> 4;               // 0..15
    int tx = tid & 15;               // 0..15

    const float* Aptr = g_u + (size_t)(m0 + lrow) * DM + lcol;
    const float* Bptr = g_X + (size_t)(n0 + lrow) * DM + lcol;

    float4 a_n = *(const float4*)(Aptr + kb);
    float4 b_n = *(const float4*)(Bptr + kb);
    #pragma unroll
    for (int q = 0; q < 4; q++) {
        As[0][lcol + q][lrow] = ((const float*)&a_n)[q];
        Bs[0][lcol + q][lrow] = ((const float*)&b_n)[q];
    }
    __syncthreads();

    float acc[4][4] = {};
    const int NIT = DCHUNK / BK;     // 8

    for (int it = 0; it < NIT; it++) {
        int cur = it & 1, nxt = cur ^ 1;
        if (it + 1 < NIT) {
            a_n = *(const float4*)(Aptr + kb + (it + 1) * BK);
            b_n = *(const float4*)(Bptr + kb + (it + 1) * BK);
        }
        #pragma unroll
        for (int kk = 0; kk < BK; kk++) {
            float4 a4 = *(const float4*)&As[cur][kk][ty * 4];
            float4 b4 = *(const float4*)&Bs[cur][kk][tx * 4];
            float a[4] = {a4.x, a4.y, a4.z, a4.w};
            float b[4] = {b4.x, b4.y, b4.z, b4.w};
            #pragma unroll
            for (int i = 0; i < 4; i++)
                #pragma unroll
                for (int j = 0; j < 4; j++)
                    acc[i][j] += a[i] * b[j];
        }
        if (it + 1 < NIT) {
            #pragma unroll
            for (int q = 0; q < 4; q++) {
                As[nxt][lcol + q][lrow] = ((const float*)&a_n)[q];
                Bs[nxt][lcol + q][lrow] = ((const float*)&b_n)[q];
            }
            __syncthreads();
        }
    }

    float* outp = g_dotp[blockIdx.z];
    #pragma unroll
    for (int i = 0; i < 4; i++) {
        int r = m0 + ty * 4 + i;
        float4 v = make_float4(acc[i][0] * 0.125f, acc[i][1] * 0.125f,
                               acc[i][2] * 0.125f, acc[i][3] * 0.125f);
        *(float4*)(outp + (size_t)r * XPAD + n0 + tx * 4) = v;
    }
}

// ---------------------------------------------------------------------------
// Kernel 3: per (h,b) softmax over valid positions + char binning.
// 512 threads: halves serial trip count of the position loops.
// ---------------------------------------------------------------------------
__global__ void softmax_bin_kernel(const int* __restrict__ data,
                                   const int* __restrict__ lengths) {
    int h = blockIdx.x;
    int b = blockIdx.y;
    int i = h * B_ + b;
    __shared__ float s[L_];
    __shared__ float dch[NCHAR];
    __shared__ float bins[NCHAR];
    __shared__ float red[16];

    int tid = threadIdx.x;       // 512
    int count = lengths[b];
    if (count < 1) count = 1;
    if (count > L_) count = L_;

    size_t base = (size_t)i * XPAD;

    if (tid < NCHAR) {
        float v = 0.f;
        #pragma unroll
        for (int z = 0; z < DSPLIT; z++) v += g_dotp[z][base + tid];
        dch[tid] = v;
        bins[tid] = 0.f;
    }
    __syncthreads();

    float lm = -CUDART_INF_F;
    for (int t = tid; t < count; t += 512) {
        int c = data[(size_t)b * L_ + t] & (NCHAR - 1);
        float v = dch[c];
        #pragma unroll
        for (int z = 0; z < DSPLIT; z++) v += g_dotp[z][base + NCHAR + t];
        s[t] = v;
        lm = fmaxf(lm, v);
    }
    #pragma unroll
    for (int off = 16; off; off >>= 1) lm = fmaxf(lm, __shfl_xor_sync(0xffffffffu, lm, off));
    if ((tid & 31) == 0) red[tid >> 5] = lm;
    __syncthreads();
    float M = -CUDART_INF_F;
    #pragma unroll
    for (int k = 0; k < 16; k++) M = fmaxf(M, red[k]);
    __syncthreads();

    float ls = 0.f;
    for (int t = tid; t < count; t += 512) {
        float e = __expf(s[t] - M);
        s[t] = e;
        ls += e;
    }
    #pragma unroll
    for (int off = 16; off; off >>= 1) ls += __shfl_xor_sync(0xffffffffu, ls, off);
    if ((tid & 31) == 0) red[tid >> 5] = ls;
    __syncthreads();
    float S = 0.f;
    #pragma unroll
    for (int k = 0; k < 16; k++) S += red[k];
    float inv = 1.f / S;

    float* WR = g_wr + base;
    for (int t = tid; t < L_; t += 512) {
        float w = 0.f;
        if (t < count) {
            w = s[t] * inv;
            atomicAdd(&bins[data[(size_t)b * L_ + t] & (NCHAR - 1)], w);
        }
        WR[NCHAR + t] = w;
    }
    __syncthreads();
    if (tid < NCHAR) WR[tid] = bins[tid];
    // pad rows of g_X are zero, so WR[XROWS..XPAD) never contributes (stays 0)
}

// ---------------------------------------------------------------------------
// Kernel 4: Y partials = WR @ X (NN GEMM), K split by YSPLIT. Double-buffered.
// grid (DM/64, NI/64, YSPLIT), 256 threads, 4x4 tile.
// ---------------------------------------------------------------------------
__global__ void y_gemm_kernel() {
    int m0 = blockIdx.y * BM;
    int n0 = blockIdx.x * BN;
    int kb = blockIdx.z * YCHUNK;

    __shared__ float As[2][BK][BM + 4];
    __shared__ float Bs[2][BK][BN + 4];

    int tid  = threadIdx.x;          // 256
    int lrow = tid >> 2;             // 0..63
    int lcol = (tid & 3) * 4;        // 0,4,8,12
    int br = tid >> 4;               // 0..15 (B tile row)
    int bc = (tid & 15) * 4;         // 0..60 (B tile col)
    int ty = tid >> 4;
    int tx = tid & 15;

    const float* Aptr = g_wr + (size_t)(m0 + lrow) * XPAD + lcol;

    float4 a_n = *(const float4*)(Aptr + kb);
    float4 b_n = *(const float4*)(g_X + (size_t)(kb + br) * DM + n0 + bc);
    #pragma unroll
    for (int q = 0; q < 4; q++)
        As[0][lcol + q][lrow] = ((const float*)&a_n)[q];
    *(float4*)&Bs[0][br][bc] = b_n;
    __syncthreads();

    float acc[4][4] = {};
    const int NIT = YCHUNK / BK;     // 10

    for (int it = 0; it < NIT; it++) {
        int cur = it & 1, nxt = cur ^ 1;
        if (it + 1 < NIT) {
            int k0 = kb + (it + 1) * BK;
            a_n = *(const float4*)(Aptr + k0);
            b_n = *(const float4*)(g_X + (size_t)(k0 + br) * DM + n0 + bc);
        }
        #pragma unroll
        for (int kk = 0; kk < BK; kk++) {
            float4 a4 = *(const float4*)&As[cur][kk][ty * 4];
            float4 b4 = *(const float4*)&Bs[cur][kk][tx * 4];
            float a[4] = {a4.x, a4.y, a4.z, a4.w};
            float b[4] = {b4.x, b4.y, b4.z, b4.w};
            #pragma unroll
            for (int ii = 0; ii < 4; ii++)
                #pragma unroll
                for (int jj = 0; jj < 4; jj++)
                    acc[ii][jj] += a[ii] * b[jj];
        }
        if (it + 1 < NIT) {
            #pragma unroll
            for (int q = 0; q < 4; q++)
                As[nxt][lcol + q][lrow] = ((const float*)&a_n)[q];
            *(float4*)&Bs[nxt][br][bc] = b_n;
            __syncthreads();
        }
    }

    float* outp = g_yp[blockIdx.z];
    #pragma unroll
    for (int ii = 0; ii < 4; ii++) {
        int r = m0 + ty * 4 + ii;
        *(float4*)(outp + (size_t)r * DM + n0 + tx * 4) =
            make_float4(acc[ii][0], acc[ii][1], acc[ii][2], acc[ii][3]);
    }
}

// ---------------------------------------------------------------------------
// Kernel 5 (fused): sum Y partials; ctx = per-head Wv_h @ y + bv; MLP head.
// One block per batch, 256 threads (8 warps). Warp w == head w.
// ---------------------------------------------------------------------------
__global__ void ctx_mlp_kernel(const float* __restrict__ Wv,
                               const float* __restrict__ bv,
                               const float* __restrict__ W1,
                               const float* __restrict__ b1,
                               const float* __restrict__ W2,
                               const float* __restrict__ b2,
                               float* __restrict__ out) {
    int b = blockIdx.x;
    __shared__ float ys[NH][DM];     // 16 KB
    __shared__ float cs[DM];
    __shared__ float hs[DM];
    __shared__ float o8[8];
    int tid = threadIdx.x;           // 256
    int w = tid >> 5, lane = tid & 31;

    // stage y: each thread owns FOUR float4 slots (covers all 1024 = NH*DM/4;
    // 4 independent partial-sum chains give ILP over the dependent g_yp loads)
    {
        float4 v[4];
        size_t off[4];
        #pragma unroll
        for (int q = 0; q < 4; q++) {
            int i4 = tid + q * 256;          // 0..1023
            int hq = i4 >> 7, eq = i4 & 127;
            off[q] = ((size_t)(hq * B_ + b) * DM) / 4 + eq;
            v[q] = make_float4(0.f, 0.f, 0.f, 0.f);
        }
        #pragma unroll
        for (int z = 0; z < YSPLIT; z++) {
            #pragma unroll
            for (int q = 0; q < 4; q++) {
                float4 p = ((const float4*)g_yp[z])[off[q]];
                v[q].x += p.x; v[q].y += p.y; v[q].z += p.z; v[q].w += p.w;
            }
        }
        #pragma unroll
        for (int q = 0; q < 4; q++) {
            int i4 = tid + q * 256;
            int hq = i4 >> 7, eq = i4 & 127;
            ((float4*)ys[hq])[eq] = v[q];
        }
    }
    __syncthreads();

    // ctx rows: warp w handles head w (rows w*64 .. w*64+63), dual-row
    const float* yv = ys[w];
    for (int jj = 0; jj < DH; jj += 2) {
        int j0 = w * DH + jj;
        const float* w0 = Wv + (size_t)j0 * DM;
        const float* w1 = w0 + DM;
        float s0 = 0.f, s1 = 0.f;
        #pragma unroll
        for (int e0 = lane * 4; e0 < DM; e0 += 128) {
            float4 y4 = *(const float4*)(yv + e0);
            float4 a0 = *(const float4*)(w0 + e0);
            float4 a1 = *(const float4*)(w1 + e0);
            s0 += a0.x * y4.x + a0.y * y4.y + a0.z * y4.z + a0.w * y4.w;
            s1 += a1.x * y4.x + a1.y * y4.y + a1.z * y4.z + a1.w * y4.w;
        }
        #pragma unroll
        for (int off = 16; off; off >>= 1) {
            s0 += __shfl_xor_sync(0xffffffffu, s0, off);
            s1 += __shfl_xor_sync(0xffffffffu, s1, off);
        }
        if (lane == 0) {
            cs[j0]     = s0 + bv[j0];
            cs[j0 + 1] = s1 + bv[j0 + 1];
        }
    }
    __syncthreads();

    // layer 1: hs = lrelu(W1 @ cs + b1), dual-row
    for (int jj = 0; jj < DH; jj += 2) {
        int j0 = w * DH + jj;
        const float* w0 = W1 + (size_t)j0 * DM;
        const float* w1 = w0 + DM;
        float s0 = 0.f, s1 = 0.f;
        #pragma unroll
        for (int e0 = lane * 4; e0 < DM; e0 += 128) {
            float4 c4 = *(const float4*)(cs + e0);
            float4 a0 = *(const float4*)(w0 + e0);
            float4 a1 = *(const float4*)(w1 + e0);
            s0 += a0.x * c4.x + a0.y * c4.y + a0.z * c4.z + a0.w * c4.w;
            s1 += a1.x * c4.x + a1.y * c4.y + a1.z * c4.z + a1.w * c4.w;
        }
        #pragma unroll
        for (int off = 16; off; off >>= 1) {
            s0 += __shfl_xor_sync(0xffffffffu, s0, off);
            s1 += __shfl_xor_sync(0xffffffffu, s1, off);
        }
        if (lane == 0) {
            float v0 = s0 + b1[j0];
            float v1 = s1 + b1[j0 + 1];
            hs[j0]     = (v0 > 0.f) ? v0 : 0.01f * v0;
            hs[j0 + 1] = (v1 > 0.f) ? v1 : 0.01f * v1;
        }
    }
    __syncthreads();

    // layer 2: warp w -> output row w
    {
        const float* wr = W2 + (size_t)w * DM;
        float s = 0.f;
        #pragma unroll
        for (int e0 = lane * 4; e0 < DM; e0 += 128) {
            float4 a = *(const float4*)(wr + e0);
            float4 h4 = *(const float4*)(hs + e0);
            s += a.x * h4.x + a.y * h4.y + a.z * h4.z + a.w * h4.w;
        }
        #pragma unroll
        for (int off = 16; off; off >>= 1) s += __shfl_xor_sync(0xffffffffu, s, off);
        if (lane == 0) {
            float v = s + b2[w];
            o8[w] = (v > 0.f) ? v : 0.f;
        }
    }
    __syncthreads();
    if (tid == 0) {
        float mv = 0.f;
        #pragma unroll
        for (int k = 0; k < 8; k++) mv += o8[k];
        mv *= 0.125f;
        out[b] = (mv > 0.f) ? mv : 0.01f * mv;
    }
}

// ---------------------------------------------------------------------------
extern "C" void kernel_launch(void* const* d_in, const int* in_sizes, int n_in,
                              void* d_out, int out_size) {
    const int* data    = (const int*)d_in[0];    // int32 (JAX x64 disabled)
    const int* lengths = (const int*)d_in[1];
    const float* emb = (const float*)d_in[2];
    const float* Wq  = (const float*)d_in[3];
    const float* bq  = (const float*)d_in[4];
    const float* Wk  = (const float*)d_in[5];
    // d_in[6] = bk: drops out of softmax (constant shift per row)
    const float* Wv  = (const float*)d_in[7];
    const float* bv  = (const float*)d_in[8];
    const float* W1  = (const float*)d_in[9];
    const float* b1  = (const float*)d_in[10];
    const float* W2  = (const float*)d_in[11];
    const float* b2  = (const float*)d_in[12];
    float* out = (float*)d_out;

    setup_kernel<<<SETUP_BLKS, 256>>>(data, lengths, emb, Wq, bq, Wk);
    d_gemm_kernel<<<dim3(XPAD / BN, NI / BM, DSPLIT), 256>>>();
    softmax_bin_kernel<<<dim3(NH, B_), 512>>>(data, lengths);
    y_gemm_kernel<<<dim3(DM / BN, NI / BM, YSPLIT), 256>>>();
    ctx_mlp_kernel<<<B_, 256>>>(Wv, bv, W1, b1, W2, b2, out);
}